// round 3
// baseline (speedup 1.0000x reference)
#include <cuda_runtime.h>
#include <cuda_bf16.h>

// Shapes fixed by the problem definition.
#define BATCH 256
#define HWPIX 1024            // 32*32
#define CHAN  256
#define NPART 4
#define PSIZE 64              // BATCH / NPART
#define EPSV  0.001f
#define NCHUNK 16             // pixel chunks per batch (64 pixels each)

// Scratch (allocation-free rule): device globals. Fully overwritten every
// replay -> no zero-init kernel, graph-replay deterministic.
__device__ float g_psum[BATCH * NCHUNK][CHAN];   // per-(batch,chunk) partials
__device__ float g_psq [BATCH * NCHUNK][CHAN];
__device__ float g_scale[NPART][CHAN];
__device__ float g_bias [NPART][CHAN];
__device__ int   g_part[BATCH];

// ---------------------------------------------------------------------------
// Kernel 1: per-(batch,chunk,channel) partial sums.
// grid=(BATCH, NCHUNK=16), block=256 -> 4096 CTAs (same shape as k_norm,
// which measured 6.2 TB/s). Thread: c4 = tid&63 (channel quad),
// psub = tid>>6 (pixel subgroup). 16 float4 loads/thread, register accumulate,
// shared reduction across 4 subgroups, plain partial writes (no atomics).
// ---------------------------------------------------------------------------
__global__ void k_stats(const float4* __restrict__ x) {
    const int b     = blockIdx.x;
    const int chunk = blockIdx.y;
    const int t     = threadIdx.x;
    const int c4    = t & 63;
    const int psub  = t >> 6;

    const float4* base = x + ((size_t)b * HWPIX + (size_t)chunk * 64) * (CHAN / 4) + c4;

    float4 s = make_float4(0.f, 0.f, 0.f, 0.f);
    float4 q = make_float4(0.f, 0.f, 0.f, 0.f);
    #pragma unroll
    for (int i = 0; i < 16; i++) {
        float4 v = base[(size_t)(i * 4 + psub) * (CHAN / 4)];
        s.x += v.x; s.y += v.y; s.z += v.z; s.w += v.w;
        q.x += v.x * v.x; q.y += v.y * v.y; q.z += v.z * v.z; q.w += v.w * v.w;
    }

    __shared__ float ssum[4][CHAN];
    __shared__ float ssq[4][CHAN];
    const int cbase = c4 * 4;
    ssum[psub][cbase + 0] = s.x; ssum[psub][cbase + 1] = s.y;
    ssum[psub][cbase + 2] = s.z; ssum[psub][cbase + 3] = s.w;
    ssq[psub][cbase + 0]  = q.x; ssq[psub][cbase + 1]  = q.y;
    ssq[psub][cbase + 2]  = q.z; ssq[psub][cbase + 3]  = q.w;
    __syncthreads();

    const int pidx = b * NCHUNK + chunk;
    g_psum[pidx][t] = ssum[0][t] + ssum[1][t] + ssum[2][t] + ssum[3][t];
    g_psq[pidx][t]  = ssq[0][t]  + ssq[1][t]  + ssq[2][t]  + ssq[3][t];
}

// ---------------------------------------------------------------------------
// Kernel 2: reduce partials -> fused scale/bias + partition map.
// grid=(NPART), block=(CHAN). Reads 8 MB of L2-hot partials; ~2-3us.
// ---------------------------------------------------------------------------
__global__ void k_finalize(const float* __restrict__ gamma,
                           const float* __restrict__ beta,
                           const int* __restrict__ perm) {
    const int p = blockIdx.x;
    const int c = threadIdx.x;

    __shared__ int sbatch[PSIZE];
    if (c < PSIZE) {
        int b = perm[p * PSIZE + c];
        sbatch[c] = b;
        g_part[b] = p;        // partition map for k_norm
    }
    __syncthreads();

    float s = 0.f, q = 0.f;
    for (int j = 0; j < PSIZE; j++) {
        const int pbase = sbatch[j] * NCHUNK;
        #pragma unroll
        for (int ch = 0; ch < NCHUNK; ch++) {
            s += g_psum[pbase + ch][c];
            q += g_psq[pbase + ch][c];
        }
    }

    const float invN = 1.0f / (float)(PSIZE * HWPIX);
    float mean = s * invN;
    float var  = q * invN - mean * mean;
    float sc   = gamma[p * CHAN + c] * rsqrtf(var + EPSV);
    g_scale[p][c] = sc;
    g_bias[p][c]  = beta[p * CHAN + c] - mean * sc;
}

// ---------------------------------------------------------------------------
// Kernel 3: normalize — exact round-1 form (78.2us @ 6231 GB/s, 78.6% DRAM):
// forward iteration, default cache ops. grid=(BATCH,16), block=256.
// ---------------------------------------------------------------------------
__global__ void k_norm(const float4* __restrict__ x, float4* __restrict__ out) {
    const int b    = blockIdx.x;
    const int t    = threadIdx.x;
    const int c4   = t & 63;
    const int psub = t >> 6;
    const int p    = g_part[b];

    const float4 sc = ((const float4*)g_scale)[p * (CHAN / 4) + c4];
    const float4 bi = ((const float4*)g_bias)[p * (CHAN / 4) + c4];

    const size_t base = (size_t)b * HWPIX * (CHAN / 4)
                      + (size_t)blockIdx.y * 64 * (CHAN / 4)
                      + c4;
    #pragma unroll
    for (int i = 0; i < 16; i++) {
        size_t idx = base + (size_t)(i * 4 + psub) * (CHAN / 4);
        float4 v = x[idx];
        v.x = v.x * sc.x + bi.x;
        v.y = v.y * sc.y + bi.y;
        v.z = v.z * sc.z + bi.z;
        v.w = v.w * sc.w + bi.w;
        out[idx] = v;
    }
}

// ---------------------------------------------------------------------------
extern "C" void kernel_launch(void* const* d_in, const int* in_sizes, int n_in,
                              void* d_out, int out_size) {
    const float* x     = (const float*)d_in[0];
    const float* gamma = (const float*)d_in[1];
    const float* beta  = (const float*)d_in[2];
    const int*   perm  = (const int*)d_in[3];

    k_stats<<<dim3(BATCH, NCHUNK), 256>>>((const float4*)x);
    k_finalize<<<NPART, CHAN>>>(gamma, beta, perm);
    k_norm<<<dim3(BATCH, 16), 256>>>((const float4*)x, (float4*)d_out);
}

// round 4
// speedup vs baseline: 1.6036x; 1.6036x over previous
#include <cuda_runtime.h>
#include <cuda_bf16.h>

// Shapes fixed by the problem definition.
#define BATCH 256
#define HWPIX 1024            // 32*32
#define CHAN  256
#define NPART 4
#define PSIZE 64              // BATCH / NPART
#define EPSV  0.001f
#define NCHUNK 16             // pixel chunks per batch (64 pixels each)

// Scratch (allocation-free rule): device globals.
__device__ float g_sum[NPART][CHAN];     // atomic accumulators (zeroed by k_prep)
__device__ float g_sq [NPART][CHAN];
__device__ float g_scale[NPART][CHAN];
__device__ float g_bias [NPART][CHAN];
__device__ int   g_part[BATCH];

// ---------------------------------------------------------------------------
// Kernel 1: build partition map from perm, zero accumulators (2 KB each).
// Zeroing is inside the graph -> replay-safe. ~2us.
// ---------------------------------------------------------------------------
__global__ void k_prep(const int* __restrict__ perm) {
    int t = threadIdx.x;             // 256 threads
    g_part[perm[t]] = t / PSIZE;
    float* s = &g_sum[0][0];
    float* q = &g_sq[0][0];
    #pragma unroll
    for (int i = 0; i < NPART; i++) {
        s[i * 256 + t] = 0.0f;
        q[i * 256 + t] = 0.0f;
    }
}

// ---------------------------------------------------------------------------
// Kernel 2: per-(partition, channel) sum / sumsq.
// grid=(BATCH, NCHUNK=16), block=256 -> 4096 CTAs (this exact load pattern
// measured 6377 GB/s, 80.5% DRAM in R3). Register accumulate 16 float4 rows,
// shared reduction across 4 pixel subgroups, then 2 atomicAdds per channel
// per block (1024 adds/address over 2048 addresses -- hidden under stream).
// ---------------------------------------------------------------------------
__global__ void k_stats(const float4* __restrict__ x) {
    const int b     = blockIdx.x;
    const int chunk = blockIdx.y;
    const int t     = threadIdx.x;
    const int c4    = t & 63;
    const int psub  = t >> 6;

    const float4* base = x + ((size_t)b * HWPIX + (size_t)chunk * 64) * (CHAN / 4) + c4;

    float4 s = make_float4(0.f, 0.f, 0.f, 0.f);
    float4 q = make_float4(0.f, 0.f, 0.f, 0.f);
    #pragma unroll
    for (int i = 0; i < 16; i++) {
        float4 v = base[(size_t)(i * 4 + psub) * (CHAN / 4)];
        s.x += v.x; s.y += v.y; s.z += v.z; s.w += v.w;
        q.x += v.x * v.x; q.y += v.y * v.y; q.z += v.z * v.z; q.w += v.w * v.w;
    }

    __shared__ float ssum[4][CHAN];
    __shared__ float ssq[4][CHAN];
    const int cbase = c4 * 4;
    ssum[psub][cbase + 0] = s.x; ssum[psub][cbase + 1] = s.y;
    ssum[psub][cbase + 2] = s.z; ssum[psub][cbase + 3] = s.w;
    ssq[psub][cbase + 0]  = q.x; ssq[psub][cbase + 1]  = q.y;
    ssq[psub][cbase + 2]  = q.z; ssq[psub][cbase + 3]  = q.w;
    __syncthreads();

    const int p = g_part[b];
    float ts = ssum[0][t] + ssum[1][t] + ssum[2][t] + ssum[3][t];
    float tq = ssq[0][t]  + ssq[1][t]  + ssq[2][t]  + ssq[3][t];
    atomicAdd(&g_sum[p][t], ts);
    atomicAdd(&g_sq[p][t], tq);
}

// ---------------------------------------------------------------------------
// Kernel 3: fold stats into fused scale/bias. Reads 2 KB. grid=(NPART,CHAN).
// ---------------------------------------------------------------------------
__global__ void k_finalize(const float* __restrict__ gamma,
                           const float* __restrict__ beta) {
    const int p = blockIdx.x;
    const int c = threadIdx.x;
    const float invN = 1.0f / (float)(PSIZE * HWPIX);
    float mean = g_sum[p][c] * invN;
    float var  = g_sq[p][c] * invN - mean * mean;
    float sc   = gamma[p * CHAN + c] * rsqrtf(var + EPSV);
    g_scale[p][c] = sc;
    g_bias[p][c]  = beta[p * CHAN + c] - mean * sc;
}

// ---------------------------------------------------------------------------
// Kernel 4: normalize — exact round-1 form (measured 78.2us @ 6231 GB/s).
// grid=(BATCH,16), block=256; forward iteration, default cache ops.
// ---------------------------------------------------------------------------
__global__ void k_norm(const float4* __restrict__ x, float4* __restrict__ out) {
    const int b    = blockIdx.x;
    const int t    = threadIdx.x;
    const int c4   = t & 63;
    const int psub = t >> 6;
    const int p    = g_part[b];

    const float4 sc = ((const float4*)g_scale)[p * (CHAN / 4) + c4];
    const float4 bi = ((const float4*)g_bias)[p * (CHAN / 4) + c4];

    const size_t base = (size_t)b * HWPIX * (CHAN / 4)
                      + (size_t)blockIdx.y * 64 * (CHAN / 4)
                      + c4;
    #pragma unroll
    for (int i = 0; i < 16; i++) {
        size_t idx = base + (size_t)(i * 4 + psub) * (CHAN / 4);
        float4 v = x[idx];
        v.x = v.x * sc.x + bi.x;
        v.y = v.y * sc.y + bi.y;
        v.z = v.z * sc.z + bi.z;
        v.w = v.w * sc.w + bi.w;
        out[idx] = v;
    }
}

// ---------------------------------------------------------------------------
extern "C" void kernel_launch(void* const* d_in, const int* in_sizes, int n_in,
                              void* d_out, int out_size) {
    const float* x     = (const float*)d_in[0];
    const float* gamma = (const float*)d_in[1];
    const float* beta  = (const float*)d_in[2];
    const int*   perm  = (const int*)d_in[3];

    k_prep<<<1, 256>>>(perm);
    k_stats<<<dim3(BATCH, NCHUNK), 256>>>((const float4*)x);
    k_finalize<<<NPART, CHAN>>>(gamma, beta);
    k_norm<<<dim3(BATCH, 16), 256>>>((const float4*)x, (float4*)d_out);
}

// round 5
// speedup vs baseline: 1.6602x; 1.0353x over previous
#include <cuda_runtime.h>
#include <cuda_bf16.h>

// Shapes fixed by the problem definition.
#define BATCH    256
#define HWPIX    1024           // 32*32
#define CHAN     256
#define NPART    4
#define PSIZE    64             // BATCH / NPART
#define EPSV     0.001f
#define NUNITS   4096           // BATCH * 16 chunks of 64 pixels
#define UNIT_PIX 64

// Scratch (allocation-free rule): device globals. Zero at module load;
// the kernel's epilogue re-zeroes g_sum/g_sq and resets g_cnt2 every run,
// so every graph replay sees identical state (deterministic).
__device__ float    g_sum[NPART][CHAN];
__device__ float    g_sq [NPART][CHAN];
__device__ unsigned g_cnt1;   // barrier-1 arrival counter (reset by last arriver)
__device__ unsigned g_rel1;   // barrier-1 release epoch (monotonic)
__device__ unsigned g_cnt2;   // epilogue arrival counter (reset by CTA 0)

// ---------------------------------------------------------------------------
// One persistent kernel: stats -> grid barrier -> normalize -> epilogue.
// grid = 4 * num_SMs, __launch_bounds__(256,4) guarantees all CTAs resident,
// making the software grid barrier deadlock-free.
// Thread layout (both phases): c4 = tid&63 (channel quad), psub = tid>>6.
// ---------------------------------------------------------------------------
__global__ void __launch_bounds__(256, 4)
k_fused(const float4* __restrict__ x, float4* __restrict__ out,
        const float* __restrict__ gamma, const float* __restrict__ beta,
        const int* __restrict__ perm) {
    const int      t    = threadIdx.x;
    const int      c4   = t & 63;
    const int      psub = t >> 6;
    const unsigned bid  = blockIdx.x;
    const unsigned nCTA = gridDim.x;

    __shared__ int   spart[BATCH];   // partition of each batch index
    __shared__ float ssum[4][CHAN];
    __shared__ float ssq [4][CHAN];

    // Build partition map per-CTA: position of b in perm, / 64.
    spart[perm[t]] = t >> 6;         // t / PSIZE
    __syncthreads();

    // ---------------- Phase 1: stats (forward unit order) ----------------
    for (unsigned u = bid; u < NUNITS; u += nCTA) {
        const int b     = (int)(u >> 4);
        const int chunk = (int)(u & 15);
        const float4* base =
            x + ((size_t)b * HWPIX + (size_t)chunk * UNIT_PIX) * (CHAN / 4) + c4;

        float4 s = make_float4(0.f, 0.f, 0.f, 0.f);
        float4 q = make_float4(0.f, 0.f, 0.f, 0.f);
        #pragma unroll
        for (int i = 0; i < 16; i++) {
            float4 v = base[(size_t)(i * 4 + psub) * (CHAN / 4)];
            s.x += v.x; s.y += v.y; s.z += v.z; s.w += v.w;
            q.x += v.x * v.x; q.y += v.y * v.y; q.z += v.z * v.z; q.w += v.w * v.w;
        }

        __syncthreads();             // protect smem reuse from previous unit
        const int cbase = c4 * 4;
        ssum[psub][cbase + 0] = s.x; ssum[psub][cbase + 1] = s.y;
        ssum[psub][cbase + 2] = s.z; ssum[psub][cbase + 3] = s.w;
        ssq[psub][cbase + 0]  = q.x; ssq[psub][cbase + 1]  = q.y;
        ssq[psub][cbase + 2]  = q.z; ssq[psub][cbase + 3]  = q.w;
        __syncthreads();

        const int p = spart[b];
        atomicAdd(&g_sum[p][t], ssum[0][t] + ssum[1][t] + ssum[2][t] + ssum[3][t]);
        atomicAdd(&g_sq[p][t],  ssq[0][t]  + ssq[1][t]  + ssq[2][t]  + ssq[3][t]);
    }

    // ---------------- Grid barrier 1 (all atomics visible) ----------------
    __syncthreads();
    if (t == 0) {
        __threadfence();
        unsigned r0  = atomicAdd(&g_rel1, 0u);       // epoch before arriving
        unsigned old = atomicAdd(&g_cnt1, 1u);
        if (old == nCTA - 1u) {
            atomicExch(&g_cnt1, 0u);                 // reset for next replay
            __threadfence();
            atomicAdd(&g_rel1, 1u);                  // release everyone
        } else {
            while (atomicAdd(&g_rel1, 0u) == r0) { __nanosleep(64); }
        }
        __threadfence();
    }
    __syncthreads();

    // ---------------- Phase 2: normalize (REVERSE unit order) -------------
    // Each CTA's last stats unit was read just before the barrier -> still in
    // L2. Norming units newest-first converts ~L2-capacity worth of reads
    // from DRAM hits to L2 hits. Scale/bias computed per-thread from the
    // (L1-hot) accumulators; identical math to the validated finalize.
    const float invN = 1.0f / (float)(PSIZE * HWPIX);
    const int kmax = (int)((NUNITS - 1u - bid) / nCTA);
    for (int k = kmax; k >= 0; k--) {
        const unsigned u = bid + (unsigned)k * nCTA;
        const int b     = (int)(u >> 4);
        const int chunk = (int)(u & 15);
        const int p     = spart[b];

        const float4 sm = *(const float4*)&g_sum[p][c4 * 4];
        const float4 sq = *(const float4*)&g_sq[p][c4 * 4];
        const float4 ga = *(const float4*)&gamma[p * CHAN + c4 * 4];
        const float4 be = *(const float4*)&beta[p * CHAN + c4 * 4];

        float mx = sm.x * invN, my = sm.y * invN, mz = sm.z * invN, mw = sm.w * invN;
        float scx = ga.x * rsqrtf(sq.x * invN - mx * mx + EPSV);
        float scy = ga.y * rsqrtf(sq.y * invN - my * my + EPSV);
        float scz = ga.z * rsqrtf(sq.z * invN - mz * mz + EPSV);
        float scw = ga.w * rsqrtf(sq.w * invN - mw * mw + EPSV);
        float bix = be.x - mx * scx, biy = be.y - my * scy;
        float biz = be.z - mz * scz, biw = be.w - mw * scw;

        const size_t base =
            ((size_t)b * HWPIX + (size_t)chunk * UNIT_PIX) * (CHAN / 4) + c4;
        #pragma unroll
        for (int i = 0; i < 16; i++) {
            size_t idx = base + (size_t)(i * 4 + psub) * (CHAN / 4);
            float4 v = x[idx];
            v.x = v.x * scx + bix;
            v.y = v.y * scy + biy;
            v.z = v.z * scz + biz;
            v.w = v.w * scw + biw;
            out[idx] = v;
        }
    }

    // ---------------- Epilogue: re-zero accumulators for next replay ------
    __syncthreads();
    if (t == 0) { __threadfence(); atomicAdd(&g_cnt2, 1u); }
    if (bid == 0) {
        if (t == 0) {
            while (atomicAdd(&g_cnt2, 0u) < nCTA) { __nanosleep(128); }
        }
        __syncthreads();
        float* s = &g_sum[0][0];
        float* q = &g_sq[0][0];
        #pragma unroll
        for (int i = 0; i < NPART; i++) {
            s[i * CHAN + t] = 0.0f;
            q[i * CHAN + t] = 0.0f;
        }
        __threadfence();
        if (t == 0) atomicExch(&g_cnt2, 0u);
    }
}

// ---------------------------------------------------------------------------
extern "C" void kernel_launch(void* const* d_in, const int* in_sizes, int n_in,
                              void* d_out, int out_size) {
    const float* x     = (const float*)d_in[0];
    const float* gamma = (const float*)d_in[1];
    const float* beta  = (const float*)d_in[2];
    const int*   perm  = (const int*)d_in[3];

    int nsm = 0;
    cudaDeviceGetAttribute(&nsm, cudaDevAttrMultiProcessorCount, 0);
    if (nsm <= 0) nsm = 148;                 // defensive fallback
    const int grid = 4 * nsm;                // __launch_bounds__(256,4) => all resident

    k_fused<<<grid, 256>>>((const float4*)x, (float4*)d_out, gamma, beta, perm);
}